// round 3
// baseline (speedup 1.0000x reference)
#include <cuda_runtime.h>

// Appro_WAConv2d: depthwise 7x7 conv with mantissa-approximation factor.
//   out[b,c,y,x] = sum_{i,j} x_pad * w * (f1+f2-1)/(f1*f2)
// where f1/f2 are the piecewise mantissa maps of x and w.
// Algebraic identity used:
//   x*w*(f1+f2-1)/(f1*f2) = u*w + s*(w/f2),  u = x/f1, s = x - u
// -> two plain depthwise convs (2 FMAs/tap), with u,s precomputed in smem
//    and {w, w/f2} precomputed per channel.

#define B_   4
#define C_   192
#define H_   56
#define W_   56
#define K_   7
#define PAD_ 3
#define SMROWS 62          // 56 + 2*3 halo
#define SROW   68          // smem row stride in floats (mult of 4, breaks bank aliasing)
#define NTHR   224

// mantissa map: a = |v|+1e-7; mant = a*2^{-floor(log2 a)} in [1,2);
// result = mant in [1,1.5) else mant/2 -> [0.75,1.5).  Pure bit manipulation:
__device__ __forceinline__ float mant_map(float v) {
    float a = fabsf(v) + 1e-7f;                 // always a normal float
    unsigned b = __float_as_uint(a);
    unsigned m = b & 0x007FFFFFu;               // mantissa bits
    unsigned e = (m & 0x00400000u) ? 0x3F000000u : 0x3F800000u; // exp 126 / 127
    return __uint_as_float(m | e);
}

__global__ __launch_bounds__(NTHR)
void waconv_kernel(const float* __restrict__ x,
                   const float* __restrict__ w,
                   float* __restrict__ out) {
    __shared__ __align__(16) float su[SMROWS * SROW];   // u = x/f1
    __shared__ __align__(16) float ss[SMROWS * SROW];   // s = x - u
    __shared__ float2 sw[K_ * K_];                      // {w, w/f2}

    const int plane = blockIdx.x;          // b*C + c
    const int c = plane % C_;
    const float* __restrict__ xp = x + (size_t)plane * (H_ * W_);
    const int tid = threadIdx.x;

    // ---- phase 1a: per-channel weights ----
    for (int k = tid; k < K_ * K_; k += NTHR) {
        float wv = w[c * (K_ * K_) + k];
        float f2 = mant_map(wv);
        sw[k] = make_float2(wv, __fdividef(wv, f2));
    }
    // ---- phase 1b: halo load + mantissa split ----
    for (int idx = tid; idx < SMROWS * SMROWS; idx += NTHR) {
        int r = idx / SMROWS;
        int q = idx - r * SMROWS;
        int iy = r - PAD_;
        int ix = q - PAD_;
        float v = 0.0f;
        if ((unsigned)iy < H_ && (unsigned)ix < W_) v = xp[iy * W_ + ix];
        float f1 = mant_map(v);
        float u  = __fdividef(v, f1);
        su[r * SROW + q] = u;
        ss[r * SROW + q] = v - u;
    }
    __syncthreads();

    // ---- phase 2: 4x4 output tile per thread (14x14 tiles) ----
    if (tid >= 196) return;
    const int ty = tid / 14;
    const int tx = tid - ty * 14;
    const int y0 = ty * 4;
    const int x0 = tx * 4;

    float acc[4][4];
#pragma unroll
    for (int a = 0; a < 4; ++a)
#pragma unroll
        for (int b = 0; b < 4; ++b) acc[a][b] = 0.0f;

#pragma unroll
    for (int t = 0; t < 10; ++t) {          // smem row = y0 + t
        const float* pu = &su[(y0 + t) * SROW + x0];   // 16B aligned
        const float* ps = &ss[(y0 + t) * SROW + x0];
        float4 u0 = *(const float4*)(pu);
        float4 u1 = *(const float4*)(pu + 4);
        float4 u2 = *(const float4*)(pu + 8);
        float4 s0 = *(const float4*)(ps);
        float4 s1 = *(const float4*)(ps + 4);
        float4 s2 = *(const float4*)(ps + 8);
        float vu[12] = {u0.x, u0.y, u0.z, u0.w, u1.x, u1.y, u1.z, u1.w,
                        u2.x, u2.y, u2.z, u2.w};
        float vs[12] = {s0.x, s0.y, s0.z, s0.w, s1.x, s1.y, s1.z, s1.w,
                        s2.x, s2.y, s2.z, s2.w};
#pragma unroll
        for (int i = 0; i < K_; ++i) {
            const int oy = t - i;           // compile-time after unroll
            if (oy < 0 || oy > 3) continue;
#pragma unroll
            for (int j = 0; j < K_; ++j) {
                float2 wv = sw[i * K_ + j];
#pragma unroll
                for (int ox = 0; ox < 4; ++ox) {
                    acc[oy][ox] = fmaf(vu[ox + j], wv.x, acc[oy][ox]);
                    acc[oy][ox] = fmaf(vs[ox + j], wv.y, acc[oy][ox]);
                }
            }
        }
    }

    float* op = out + (size_t)plane * (H_ * W_) + y0 * W_ + x0;
#pragma unroll
    for (int oy = 0; oy < 4; ++oy) {
        float4 r = make_float4(acc[oy][0], acc[oy][1], acc[oy][2], acc[oy][3]);
        *(float4*)(op + oy * W_) = r;
    }
}

extern "C" void kernel_launch(void* const* d_in, const int* in_sizes, int n_in,
                              void* d_out, int out_size) {
    const float* x  = (const float*)d_in[0];   // (4,192,56,56) f32
    const float* wt = (const float*)d_in[1];   // (192,1,7,7)  f32
    float* out = (float*)d_out;                // (4,192,56,56) f32
    (void)in_sizes; (void)n_in; (void)out_size;
    waconv_kernel<<<B_ * C_, NTHR>>>(x, wt, out);
}

// round 4
// speedup vs baseline: 1.0102x; 1.0102x over previous
#include <cuda_runtime.h>

// Appro_WAConv2d: depthwise 7x7 conv with mantissa-approximation factor.
//   out[b,c,y,x] = sum_{i,j} x_pad * w * (f1+f2-1)/(f1*f2)
// where f1/f2 are the piecewise mantissa maps of x and w.
// Algebraic identity used:
//   x*w*(f1+f2-1)/(f1*f2) = u*w + s*(w/f2),  u = x/f1, s = x - u
// -> two plain depthwise convs (2 FMAs/tap), with u,s precomputed in smem
//    and {w, w/f2} precomputed per channel.

#define B_   4
#define C_   192
#define H_   56
#define W_   56
#define K_   7
#define PAD_ 3
#define SMROWS 62          // 56 + 2*3 halo
#define SROW   68          // smem row stride in floats (mult of 4, breaks bank aliasing)
#define NTHR   224

// mantissa map: a = |v|+1e-7; mant = a*2^{-floor(log2 a)} in [1,2);
// result = mant in [1,1.5) else mant/2 -> [0.75,1.5).  Pure bit manipulation:
__device__ __forceinline__ float mant_map(float v) {
    float a = fabsf(v) + 1e-7f;                 // always a normal float
    unsigned b = __float_as_uint(a);
    unsigned m = b & 0x007FFFFFu;               // mantissa bits
    unsigned e = (m & 0x00400000u) ? 0x3F000000u : 0x3F800000u; // exp 126 / 127
    return __uint_as_float(m | e);
}

__global__ __launch_bounds__(NTHR)
void waconv_kernel(const float* __restrict__ x,
                   const float* __restrict__ w,
                   float* __restrict__ out) {
    __shared__ __align__(16) float su[SMROWS * SROW];   // u = x/f1
    __shared__ __align__(16) float ss[SMROWS * SROW];   // s = x - u
    __shared__ float2 sw[K_ * K_];                      // {w, w/f2}

    const int plane = blockIdx.x;          // b*C + c
    const int c = plane % C_;
    const float* __restrict__ xp = x + (size_t)plane * (H_ * W_);
    const int tid = threadIdx.x;

    // ---- phase 1a: per-channel weights ----
    for (int k = tid; k < K_ * K_; k += NTHR) {
        float wv = w[c * (K_ * K_) + k];
        float f2 = mant_map(wv);
        sw[k] = make_float2(wv, __fdividef(wv, f2));
    }
    // ---- phase 1b: halo load + mantissa split ----
    for (int idx = tid; idx < SMROWS * SMROWS; idx += NTHR) {
        int r = idx / SMROWS;
        int q = idx - r * SMROWS;
        int iy = r - PAD_;
        int ix = q - PAD_;
        float v = 0.0f;
        if ((unsigned)iy < H_ && (unsigned)ix < W_) v = xp[iy * W_ + ix];
        float f1 = mant_map(v);
        float u  = __fdividef(v, f1);
        su[r * SROW + q] = u;
        ss[r * SROW + q] = v - u;
    }
    __syncthreads();

    // ---- phase 2: 4x4 output tile per thread (14x14 tiles) ----
    if (tid >= 196) return;
    const int ty = tid / 14;
    const int tx = tid - ty * 14;
    const int y0 = ty * 4;
    const int x0 = tx * 4;

    float acc[4][4];
#pragma unroll
    for (int a = 0; a < 4; ++a)
#pragma unroll
        for (int b = 0; b < 4; ++b) acc[a][b] = 0.0f;

#pragma unroll
    for (int t = 0; t < 10; ++t) {          // smem row = y0 + t
        const float* pu = &su[(y0 + t) * SROW + x0];   // 16B aligned
        const float* ps = &ss[(y0 + t) * SROW + x0];
        float4 u0 = *(const float4*)(pu);
        float4 u1 = *(const float4*)(pu + 4);
        float4 u2 = *(const float4*)(pu + 8);
        float4 s0 = *(const float4*)(ps);
        float4 s1 = *(const float4*)(ps + 4);
        float4 s2 = *(const float4*)(ps + 8);
        float vu[12] = {u0.x, u0.y, u0.z, u0.w, u1.x, u1.y, u1.z, u1.w,
                        u2.x, u2.y, u2.z, u2.w};
        float vs[12] = {s0.x, s0.y, s0.z, s0.w, s1.x, s1.y, s1.z, s1.w,
                        s2.x, s2.y, s2.z, s2.w};
#pragma unroll
        for (int i = 0; i < K_; ++i) {
            const int oy = t - i;           // compile-time after unroll
            if (oy < 0 || oy > 3) continue;
#pragma unroll
            for (int j = 0; j < K_; ++j) {
                float2 wv = sw[i * K_ + j];
#pragma unroll
                for (int ox = 0; ox < 4; ++ox) {
                    acc[oy][ox] = fmaf(vu[ox + j], wv.x, acc[oy][ox]);
                    acc[oy][ox] = fmaf(vs[ox + j], wv.y, acc[oy][ox]);
                }
            }
        }
    }

    float* op = out + (size_t)plane * (H_ * W_) + y0 * W_ + x0;
#pragma unroll
    for (int oy = 0; oy < 4; ++oy) {
        float4 r = make_float4(acc[oy][0], acc[oy][1], acc[oy][2], acc[oy][3]);
        *(float4*)(op + oy * W_) = r;
    }
}

extern "C" void kernel_launch(void* const* d_in, const int* in_sizes, int n_in,
                              void* d_out, int out_size) {
    const float* x  = (const float*)d_in[0];   // (4,192,56,56) f32
    const float* wt = (const float*)d_in[1];   // (192,1,7,7)  f32
    float* out = (float*)d_out;                // (4,192,56,56) f32
    (void)in_sizes; (void)n_in; (void)out_size;
    waconv_kernel<<<B_ * C_, NTHR>>>(x, wt, out);
}